// round 2
// baseline (speedup 1.0000x reference)
#include <cuda_runtime.h>
#include <math.h>

#define S_LEN 2048
#define HID   2048
#define NH    16
#define NKV   4
#define HD    128
#define QKV_N 3072
#define SCALE 0.08838834764831845f   // 128^-0.5

// Scratch (device globals — no allocation allowed)
__device__ float g_qkv[S_LEN * QKV_N];    // [S, 3072] = [q(2048) | k(512) | v(512)]
__device__ float g_attn[S_LEN * HID];     // attention output [S, 2048]

// ---------------------------------------------------------------------------
// SGEMM: C[M,N] = A[M,K] @ B[K,N], all row-major, M,N % 128 == 0, K % 8 == 0
// 128x128 block tile, BK=8, 256 threads, 8x8 register tile per thread.
// ---------------------------------------------------------------------------
__global__ __launch_bounds__(256) void sgemm_kernel(
    const float* __restrict__ A, const float* __restrict__ B,
    float* __restrict__ C, int M, int N, int K)
{
    __shared__ float As[8][132];   // transposed A tile: As[k][m]
    __shared__ float Bs[8][132];

    const int tid = threadIdx.x;
    const int bx = blockIdx.x, by = blockIdx.y;
    const int tx = tid & 15, ty = tid >> 4;

    // global load mapping
    const int rowA = by * 128 + (tid >> 1);
    const int kcA  = (tid & 1) * 4;
    const int kbB  = tid >> 5;
    const int cB   = (tid & 31) * 4;

    const float* Aptr = A + (size_t)rowA * K + kcA;
    const float* Bptr = B + (size_t)kbB * N + bx * 128 + cB;

    float acc[8][8];
    #pragma unroll
    for (int i = 0; i < 8; i++)
        #pragma unroll
        for (int j = 0; j < 8; j++) acc[i][j] = 0.0f;

    float a_frag[8], b_frag[8];

    for (int k0 = 0; k0 < K; k0 += 8) {
        float4 a = *(const float4*)(Aptr + k0);
        As[kcA + 0][tid >> 1] = a.x;
        As[kcA + 1][tid >> 1] = a.y;
        As[kcA + 2][tid >> 1] = a.z;
        As[kcA + 3][tid >> 1] = a.w;
        *(float4*)&Bs[kbB][cB] = *(const float4*)(Bptr + (size_t)k0 * N);
        __syncthreads();

        #pragma unroll
        for (int kk = 0; kk < 8; kk++) {
            *(float4*)&a_frag[0] = *(float4*)&As[kk][ty * 8];
            *(float4*)&a_frag[4] = *(float4*)&As[kk][ty * 8 + 4];
            *(float4*)&b_frag[0] = *(float4*)&Bs[kk][tx * 8];
            *(float4*)&b_frag[4] = *(float4*)&Bs[kk][tx * 8 + 4];
            #pragma unroll
            for (int i = 0; i < 8; i++)
                #pragma unroll
                for (int j = 0; j < 8; j++)
                    acc[i][j] += a_frag[i] * b_frag[j];
        }
        __syncthreads();
    }

    #pragma unroll
    for (int i = 0; i < 8; i++) {
        int r = by * 128 + ty * 8 + i;
        float* cp = C + (size_t)r * N + bx * 128 + tx * 8;
        *(float4*)cp       = make_float4(acc[i][0], acc[i][1], acc[i][2], acc[i][3]);
        *(float4*)(cp + 4) = make_float4(acc[i][4], acc[i][5], acc[i][6], acc[i][7]);
    }
}

// ---------------------------------------------------------------------------
// RoPE (faithful to the reference's double-trig):
//   i = d % 64; f = p * 10000^(-2i/128)
//   e = (d < 64) ? sin(f) : cos(f);  c = cos(e); s = sin(e)
//   partner = (d < 64) ? -x[d+64] : x[d-64]
//   x'[d] = x[d]*c + partner*s
// Double-precision trig: immune to fast-math sinf at args up to 2047 rad.
// One block = one (position, head) vector of 128 dims. heads 0..15 = q, 16..19 = k.
// ---------------------------------------------------------------------------
__global__ void rope_kernel(const int* __restrict__ pos, float* __restrict__ qkv)
{
    const int s = blockIdx.x;
    const int head = blockIdx.y;
    const int d = threadIdx.x;             // 0..127
    const int base = (head < NH) ? head * HD : HID + (head - NH) * HD;
    float* row = qkv + (size_t)s * QKV_N + base;

    float x  = row[d];
    float xp = row[d ^ 64];
    __syncthreads();   // all reads before any writes

    const int i = d & 63;
    double p   = (double)pos[s];
    double inv = exp(-((double)(2 * i) / 128.0) * log(10000.0));
    double f   = p * inv;
    double e   = (d < 64) ? sin(f) : cos(f);
    float  c   = (float)cos(e);
    float  sn  = (float)sin(e);
    float  partner = (d < 64) ? -xp : xp;
    row[d] = x * c + partner * sn;
}

// ---------------------------------------------------------------------------
// Flash attention (fp32, causal, GQA rep=4).
// Grid: (32 q-tiles, 16 heads). Block: 256 threads (8 warps).
// Each block: 64 queries of one head. Each warp: 8 query rows.
// Each lane: 2 keys of the 64-key tile (lane, lane+32) for scores;
//            4 output dims (lane*4..lane*4+3) for the P·V accumulation.
// ---------------------------------------------------------------------------
#define BQ  64
#define PAD 132
#define SMEM_FLASH ((3 * BQ * PAD + BQ * BQ) * 4)

__global__ __launch_bounds__(256) void flash_kernel(
    const float* __restrict__ qkv, float* __restrict__ attn)
{
    extern __shared__ float sm[];
    float* Qs = sm;                    // [64][132]
    float* Ks = Qs + BQ * PAD;         // [64][132]
    float* Vs = Ks + BQ * PAD;         // [64][132]
    float* Ps = Vs + BQ * PAD;         // [64 qrows][64 keys]

    const int qt = blockIdx.x;
    const int h  = blockIdx.y;
    const int hk = h >> 2;
    const int tid = threadIdx.x;
    const int w = tid >> 5, lane = tid & 31;

    // load Q tile (post-RoPE)
    #pragma unroll
    for (int t = 0; t < 8; t++) {
        int idx = tid + t * 256;                // 0..2047 float4s
        int r = idx >> 5, c4 = idx & 31;
        *(float4*)(Qs + r * PAD + c4 * 4) =
            *(const float4*)(qkv + (size_t)(qt * BQ + r) * QKV_N + h * HD + c4 * 4);
    }

    float m[8], l[8], O[8][4];
    #pragma unroll
    for (int q = 0; q < 8; q++) {
        m[q] = -1e30f; l[q] = 0.0f;
        O[q][0] = O[q][1] = O[q][2] = O[q][3] = 0.0f;
    }

    for (int kt = 0; kt <= qt; kt++) {
        __syncthreads();   // previous tile fully consumed
        #pragma unroll
        for (int t = 0; t < 8; t++) {
            int idx = tid + t * 256;
            int r = idx >> 5, c4 = idx & 31;
            const float* src = qkv + (size_t)(kt * BQ + r) * QKV_N + hk * HD + c4 * 4;
            *(float4*)(Ks + r * PAD + c4 * 4) = *(const float4*)(src + HID);          // K
            *(float4*)(Vs + r * PAD + c4 * 4) = *(const float4*)(src + HID + 512);    // V
        }
        __syncthreads();

        // scores: this warp's 8 queries x this lane's 2 keys
        float s0[8], s1[8];
        #pragma unroll
        for (int q = 0; q < 8; q++) { s0[q] = 0.0f; s1[q] = 0.0f; }
        const float4* K0 = (const float4*)(Ks + lane * PAD);
        const float4* K1 = (const float4*)(Ks + (lane + 32) * PAD);
        #pragma unroll 4
        for (int d4 = 0; d4 < 32; d4++) {
            float4 k0 = K0[d4], k1 = K1[d4];
            #pragma unroll
            for (int q = 0; q < 8; q++) {
                float4 qv = *(const float4*)(Qs + (w * 8 + q) * PAD + d4 * 4);
                s0[q] += qv.x * k0.x + qv.y * k0.y + qv.z * k0.z + qv.w * k0.w;
                s1[q] += qv.x * k1.x + qv.y * k1.y + qv.z * k1.z + qv.w * k1.w;
            }
        }

        const int kg0 = kt * BQ + lane;
        const int kg1 = kt * BQ + lane + 32;
        #pragma unroll
        for (int q = 0; q < 8; q++) {
            int qg = qt * BQ + w * 8 + q;
            float v0 = (kg0 > qg) ? -1e30f : s0[q] * SCALE;
            float v1 = (kg1 > qg) ? -1e30f : s1[q] * SCALE;
            float t = fmaxf(v0, v1);
            #pragma unroll
            for (int off = 16; off; off >>= 1)
                t = fmaxf(t, __shfl_xor_sync(0xffffffffu, t, off));
            float nm = fmaxf(m[q], t);
            float p0 = __expf(v0 - nm);
            float p1 = __expf(v1 - nm);
            float ps = p0 + p1;
            #pragma unroll
            for (int off = 16; off; off >>= 1)
                ps += __shfl_xor_sync(0xffffffffu, ps, off);
            float corr = __expf(m[q] - nm);
            l[q] = l[q] * corr + ps;
            m[q] = nm;
            O[q][0] *= corr; O[q][1] *= corr; O[q][2] *= corr; O[q][3] *= corr;
            Ps[(w * 8 + q) * 64 + lane]      = p0;
            Ps[(w * 8 + q) * 64 + lane + 32] = p1;
        }
        __syncwarp();

        // O += P @ V   (lane owns dims lane*4..+3)
        #pragma unroll 4
        for (int k = 0; k < BQ; k++) {
            float4 v = *(const float4*)(Vs + k * PAD + lane * 4);
            #pragma unroll
            for (int q = 0; q < 8; q++) {
                float p = Ps[(w * 8 + q) * 64 + k];
                O[q][0] += p * v.x; O[q][1] += p * v.y;
                O[q][2] += p * v.z; O[q][3] += p * v.w;
            }
        }
        __syncwarp();
    }

    #pragma unroll
    for (int q = 0; q < 8; q++) {
        float inv = 1.0f / l[q];
        int qg = qt * BQ + w * 8 + q;
        *(float4*)(attn + (size_t)qg * HID + h * HD + lane * 4) =
            make_float4(O[q][0] * inv, O[q][1] * inv, O[q][2] * inv, O[q][3] * inv);
    }
}

// ---------------------------------------------------------------------------
extern "C" void kernel_launch(void* const* d_in, const int* in_sizes, int n_in,
                              void* d_out, int out_size)
{
    const float* X   = (const float*)d_in[0];   // hidden_states [1,2048,2048]
    // d_in[1] = attention_mask (pure causal additive; applied analytically)
    const int*   pos = (const int*)d_in[2];     // position_ids [1,2048] int32
    const float* Wa  = (const float*)d_in[3];   // W_attn [2048,3072]
    const float* Wp  = (const float*)d_in[4];   // W_proj [2048,2048]
    float* out = (float*)d_out;

    float *qkv, *attn;
    cudaGetSymbolAddress((void**)&qkv,  g_qkv);
    cudaGetSymbolAddress((void**)&attn, g_attn);

    // 1) QKV = X @ W_attn
    sgemm_kernel<<<dim3(QKV_N / 128, S_LEN / 128), 256>>>(X, Wa, qkv, S_LEN, QKV_N, HID);

    // 2) RoPE in place on q (16 heads) + k (4 heads)
    rope_kernel<<<dim3(S_LEN, NH + NKV), HD>>>(pos, qkv);

    // 3) causal flash attention -> attn [S, 2048]
    cudaFuncSetAttribute(flash_kernel, cudaFuncAttributeMaxDynamicSharedMemorySize, SMEM_FLASH);
    flash_kernel<<<dim3(S_LEN / BQ, NH), 256, SMEM_FLASH>>>(qkv, attn);

    // 4) out = attn @ W_proj
    sgemm_kernel<<<dim3(HID / 128, S_LEN / 128), 256>>>(attn, Wp, out, S_LEN, HID, HID);
}

// round 11
// speedup vs baseline: 1.2765x; 1.2765x over previous
#include <cuda_runtime.h>
#include <cuda_bf16.h>
#include <cstdint>
#include <math.h>

#define S_LEN 2048
#define HID   2048
#define NH    16
#define NKV   4
#define HD    128
#define QKV_N 3072
#define SCALE 0.08838834764831845f   // 128^-0.5

// ---------------------------------------------------------------------------
// Scratch (device globals — no allocation allowed)
// ---------------------------------------------------------------------------
__device__ float g_qkv[S_LEN * QKV_N];          // [S, 3072] = [q | k | v]
__device__ float g_attn[S_LEN * HID];           // attention output [S, 2048]

__device__ __nv_bfloat16 g_Xhi[S_LEN * HID];
__device__ __nv_bfloat16 g_Xlo[S_LEN * HID];
__device__ __nv_bfloat16 g_WaThi[QKV_N * HID];  // Wa^T [3072,2048]
__device__ __nv_bfloat16 g_WaTlo[QKV_N * HID];
__device__ __nv_bfloat16 g_WpThi[HID * HID];    // Wp^T [2048,2048]
__device__ __nv_bfloat16 g_WpTlo[HID * HID];
__device__ __nv_bfloat16 g_Ahi[S_LEN * HID];
__device__ __nv_bfloat16 g_Alo[S_LEN * HID];

// ---------------------------------------------------------------------------
// Helpers (baseline ISA only: ldmatrix / mma.sync / cp.async — no tcgen05)
// ---------------------------------------------------------------------------
__device__ __forceinline__ uint32_t smem_u32(const void* p) {
    uint32_t a;
    asm("{ .reg .u64 t; cvta.to.shared.u64 t, %1; cvt.u32.u64 %0, t; }" : "=r"(a) : "l"(p));
    return a;
}
__device__ __forceinline__ uint32_t swz128(uint32_t b) { return b ^ ((b >> 3) & 0x70); }

#define LDSM_X4(r, a) \
    asm volatile("ldmatrix.sync.aligned.m8n8.x4.shared.b16 {%0,%1,%2,%3}, [%4];" \
        : "=r"((r)[0]), "=r"((r)[1]), "=r"((r)[2]), "=r"((r)[3]) : "r"(a))

#define MMA_BF16(d, a, b0, b1) \
    asm volatile("mma.sync.aligned.m16n8k16.row.col.f32.bf16.bf16.f32 " \
        "{%0,%1,%2,%3}, {%4,%5,%6,%7}, {%8,%9}, {%0,%1,%2,%3};" \
        : "+f"((d)[0]), "+f"((d)[1]), "+f"((d)[2]), "+f"((d)[3]) \
        : "r"((a)[0]), "r"((a)[1]), "r"((a)[2]), "r"((a)[3]), "r"(b0), "r"(b1))

#define CP16(dst, src) \
    asm volatile("cp.async.cg.shared.global [%0], [%1], 16;" :: "r"(dst), "l"(src))
#define CP_COMMIT() asm volatile("cp.async.commit_group;" ::: "memory")
#define CP_WAIT1()  asm volatile("cp.async.wait_group 1;" ::: "memory")

// ---------------------------------------------------------------------------
// Prep: fp32 -> (hi, lo) bf16 split, elementwise
// ---------------------------------------------------------------------------
__global__ void split_kernel(const float* __restrict__ x,
                             __nv_bfloat16* __restrict__ hi,
                             __nv_bfloat16* __restrict__ lo, int n)
{
    int i = blockIdx.x * blockDim.x + threadIdx.x;
    if (i >= n) return;
    float v = x[i];
    __nv_bfloat16 h = __float2bfloat16_rn(v);
    hi[i] = h;
    lo[i] = __float2bfloat16_rn(v - __bfloat162float(h));
}

// Transpose + split: W[K,N] fp32 -> T{hi,lo}[N,K] bf16
__global__ void transpose_split_kernel(const float* __restrict__ W,
                                       __nv_bfloat16* __restrict__ Thi,
                                       __nv_bfloat16* __restrict__ Tlo, int K, int N)
{
    __shared__ float t[32][33];
    int k0 = blockIdx.x * 32, n0 = blockIdx.y * 32;
    int tx = threadIdx.x, ty = threadIdx.y;
    #pragma unroll
    for (int i = 0; i < 4; i++)
        t[ty + i * 8][tx] = W[(size_t)(k0 + ty + i * 8) * N + n0 + tx];
    __syncthreads();
    #pragma unroll
    for (int i = 0; i < 4; i++) {
        float v = t[tx][ty + i * 8];
        __nv_bfloat16 h = __float2bfloat16_rn(v);
        size_t o = (size_t)(n0 + ty + i * 8) * K + k0 + tx;
        Thi[o] = h;
        Tlo[o] = __float2bfloat16_rn(v - __bfloat162float(h));
    }
}

// ---------------------------------------------------------------------------
// GEMM via mma.sync bf16 with 3-term split: C = Ahi*Bhi + Ahi*Blo + Alo*Bhi
// A[M,K] row-major (hi/lo), B given transposed Bt[N,K] row-major (hi/lo), C fp32.
// CTA 128x128, K-chunk 64, 8 warps (2x4), warp tile 64x32, cp.async double buffer.
// smem stage: [Ahi 16K | Alo 16K | Bhi 16K | Blo 16K], 2 stages = 128KB.
// ---------------------------------------------------------------------------
#define GT      16384
#define GSTAGE  65536
#define GSMEM   131072

__global__ __launch_bounds__(256) void gemm_bf16x3_kernel(
    const __nv_bfloat16* __restrict__ Ahi, const __nv_bfloat16* __restrict__ Alo,
    const __nv_bfloat16* __restrict__ Bhi, const __nv_bfloat16* __restrict__ Blo,
    float* __restrict__ C, int M, int N, int K)
{
    extern __shared__ char smc[];
    const uint32_t smem = smem_u32(smc);
    const int tid = threadIdx.x;
    const int wid = tid >> 5, lane = tid & 31;
    const int m0 = blockIdx.y * 128, n0 = blockIdx.x * 128;
    const int wm = wid & 1, wn = wid >> 1;

    float acc[4][4][4];
    #pragma unroll
    for (int a = 0; a < 4; a++)
        #pragma unroll
        for (int b = 0; b < 4; b++)
            #pragma unroll
            for (int c = 0; c < 4; c++) acc[a][b][c] = 0.0f;

    const int nkt = K >> 6;

    // stage fill: 4 tiles of 128 rows x 128B, 16 cp.async of 16B per thread
    auto fill = [&](int s, int kt) {
        #pragma unroll
        for (int t = 0; t < 4; t++) {
            int idx = tid + t * 256;           // 0..1023
            int row = idx >> 3, c16 = idx & 7;
            uint32_t dst = smem + s * GSTAGE + swz128(row * 128 + c16 * 16);
            size_t ka = (size_t)(m0 + row) * K + kt * 64 + c16 * 8;
            size_t kb = (size_t)(n0 + row) * K + kt * 64 + c16 * 8;
            CP16(dst,          Ahi + ka);
            CP16(dst + GT,     Alo + ka);
            CP16(dst + 2 * GT, Bhi + kb);
            CP16(dst + 3 * GT, Blo + kb);
        }
        CP_COMMIT();
    };

    fill(0, 0);

    const int r16 = lane & 15, chi = lane >> 4;

    for (int kt = 0; kt < nkt; kt++) {
        if (kt + 1 < nkt) fill((kt + 1) & 1, kt + 1);
        else CP_COMMIT();                      // empty group keeps counting uniform
        CP_WAIT1();
        __syncthreads();

        const uint32_t Ab = smem + (kt & 1) * GSTAGE;
        const uint32_t Bb = Ab + 2 * GT;

        #pragma unroll
        for (int ks = 0; ks < 4; ks++) {
            uint32_t a_hi[4][4], a_lo[4][4], b_hi[2][4], b_lo[2][4];
            #pragma unroll
            for (int mt = 0; mt < 4; mt++) {
                uint32_t off = swz128((wm * 64 + mt * 16 + r16) * 128 + (ks * 2 + chi) * 16);
                LDSM_X4(a_hi[mt], Ab + off);
                LDSM_X4(a_lo[mt], Ab + GT + off);
            }
            #pragma unroll
            for (int h = 0; h < 2; h++) {
                uint32_t off = swz128((wn * 32 + h * 16 + r16) * 128 + (ks * 2 + chi) * 16);
                LDSM_X4(b_hi[h], Bb + off);
                LDSM_X4(b_lo[h], Bb + GT + off);
            }
            #pragma unroll
            for (int mt = 0; mt < 4; mt++)
                #pragma unroll
                for (int nt = 0; nt < 4; nt++) {
                    int h = nt >> 1, o = nt & 1;
                    MMA_BF16(acc[mt][nt], a_hi[mt], b_hi[h][o], b_hi[h][o + 2]);
                    MMA_BF16(acc[mt][nt], a_hi[mt], b_lo[h][o], b_lo[h][o + 2]);
                    MMA_BF16(acc[mt][nt], a_lo[mt], b_hi[h][o], b_hi[h][o + 2]);
                }
        }
        __syncthreads();
    }

    #pragma unroll
    for (int mt = 0; mt < 4; mt++) {
        int row = m0 + wm * 64 + mt * 16 + (lane >> 2);
        #pragma unroll
        for (int nt = 0; nt < 4; nt++) {
            int col = n0 + wn * 32 + nt * 8 + (lane & 3) * 2;
            *(float2*)&C[(size_t)row * N + col] =
                make_float2(acc[mt][nt][0], acc[mt][nt][1]);
            *(float2*)&C[(size_t)(row + 8) * N + col] =
                make_float2(acc[mt][nt][2], acc[mt][nt][3]);
        }
    }
}

// ---------------------------------------------------------------------------
// RoPE (faithful double-trig, fp64 — safe vs fast-math)
// ---------------------------------------------------------------------------
__global__ void rope_kernel(const int* __restrict__ pos, float* __restrict__ qkv)
{
    const int s = blockIdx.x;
    const int head = blockIdx.y;
    const int d = threadIdx.x;             // 0..127
    const int base = (head < NH) ? head * HD : HID + (head - NH) * HD;
    float* row = qkv + (size_t)s * QKV_N + base;

    float x  = row[d];
    float xp = row[d ^ 64];
    __syncthreads();

    const int i = d & 63;
    double p   = (double)pos[s];
    double inv = exp(-((double)(2 * i) / 128.0) * log(10000.0));
    double f   = p * inv;
    double e   = (d < 64) ? sin(f) : cos(f);
    float  c   = (float)cos(e);
    float  sn  = (float)sin(e);
    float  partner = (d < 64) ? -xp : xp;
    row[d] = x * c + partner * sn;
}

// ---------------------------------------------------------------------------
// Flash attention (fp32, causal, GQA rep=4), XOR-swizzled smem (conflict-free)
// Grid (32 q-tiles, 16 heads), 256 threads, 2 blocks/SM. Warp = 8 query rows;
// lane = 2 keys for scores, 4 output dims for P·V.
// ---------------------------------------------------------------------------
#define BQ 64
#define SMEM_FLASH ((3 * BQ * HD + BQ * BQ) * 4)   // 114688

__global__ __launch_bounds__(256, 2) void flash_kernel(
    const float* __restrict__ qkv, float* __restrict__ attn)
{
    extern __shared__ float smf[];
    float* Qs = smf;                   // [64][128] swizzled
    float* Ks = Qs + BQ * HD;
    float* Vs = Ks + BQ * HD;
    float* Ps = Vs + BQ * HD;          // [64][64]

    const int qt = blockIdx.x;
    const int h  = blockIdx.y;
    const int hk = h >> 2;
    const int tid = threadIdx.x;
    const int w = tid >> 5, lane = tid & 31;
    const int l7 = lane & 7;

    #pragma unroll
    for (int t = 0; t < 8; t++) {
        int idx = tid + t * 256;
        int r = idx >> 5, c4 = idx & 31;
        int cs = (c4 & 24) | ((c4 ^ r) & 7);
        *(float4*)(Qs + r * HD + cs * 4) =
            *(const float4*)(qkv + (size_t)(qt * BQ + r) * QKV_N + h * HD + c4 * 4);
    }

    float m[8], l[8], O[8][4];
    #pragma unroll
    for (int q = 0; q < 8; q++) {
        m[q] = -1e30f; l[q] = 0.0f;
        O[q][0] = O[q][1] = O[q][2] = O[q][3] = 0.0f;
    }

    for (int kt = 0; kt <= qt; kt++) {
        __syncthreads();
        #pragma unroll
        for (int t = 0; t < 8; t++) {
            int idx = tid + t * 256;
            int r = idx >> 5, c4 = idx & 31;
            int cs = (c4 & 24) | ((c4 ^ r) & 7);
            const float* src = qkv + (size_t)(kt * BQ + r) * QKV_N + hk * HD + c4 * 4;
            *(float4*)(Ks + r * HD + cs * 4) = *(const float4*)(src + HID);        // K
            *(float4*)(Vs + r * HD + cs * 4) = *(const float4*)(src + HID + 512);  // V
        }
        __syncthreads();

        float s0[8], s1[8];
        #pragma unroll
        for (int q = 0; q < 8; q++) { s0[q] = 0.0f; s1[q] = 0.0f; }
        const float* K0 = Ks + lane * HD;
        const float* K1 = Ks + (lane + 32) * HD;
        #pragma unroll 4
        for (int d4 = 0; d4 < 32; d4++) {
            int kc = ((d4 & 24) | ((d4 ^ l7) & 7)) * 4;
            float4 k0 = *(const float4*)(K0 + kc);
            float4 k1 = *(const float4*)(K1 + kc);
            #pragma unroll
            for (int q = 0; q < 8; q++) {
                int qc = ((d4 & 24) | ((d4 ^ q) & 7)) * 4;
                float4 qv = *(const float4*)(Qs + (w * 8 + q) * HD + qc);
                s0[q] += qv.x * k0.x + qv.y * k0.y + qv.z * k0.z + qv.w * k0.w;
                s1[q] += qv.x * k1.x + qv.y * k1.y + qv.z * k1.z + qv.w * k1.w;
            }
        }

        const int kg0 = kt * BQ + lane;
        const int kg1 = kt * BQ + lane + 32;
        #pragma unroll
        for (int q = 0; q < 8; q++) {
            int qg = qt * BQ + w * 8 + q;
            float v0 = (kg0 > qg) ? -1e30f : s0[q] * SCALE;
            float v1 = (kg1 > qg) ? -1e30f : s1[q] * SCALE;
            float t = fmaxf(v0, v1);
            #pragma unroll
            for (int off = 16; off; off >>= 1)
                t = fmaxf(t, __shfl_xor_sync(0xffffffffu, t, off));
            float nm = fmaxf(m[q], t);
            float p0 = __expf(v0 - nm);
            float p1 = __expf(v1 - nm);
            float ps = p0 + p1;
            #pragma unroll
            for (int off = 16; off; off >>= 1)
                ps += __shfl_xor_sync(0xffffffffu, ps, off);
            float corr = __expf(m[q] - nm);
            l[q] = l[q] * corr + ps;
            m[q] = nm;
            O[q][0] *= corr; O[q][1] *= corr; O[q][2] *= corr; O[q][3] *= corr;
            Ps[(w * 8 + q) * 64 + lane]      = p0;
            Ps[(w * 8 + q) * 64 + lane + 32] = p1;
        }
        __syncwarp();

        #pragma unroll 4
        for (int k = 0; k < BQ; k++) {
            int vc = ((lane & 24) | ((lane ^ k) & 7)) * 4;
            float4 v = *(const float4*)(Vs + k * HD + vc);
            #pragma unroll
            for (int q = 0; q < 8; q++) {
                float p = Ps[(w * 8 + q) * 64 + k];
                O[q][0] += p * v.x; O[q][1] += p * v.y;
                O[q][2] += p * v.z; O[q][3] += p * v.w;
            }
        }
        __syncwarp();
    }

    #pragma unroll
    for (int q = 0; q < 8; q++) {
        float inv = 1.0f / l[q];
        int qg = qt * BQ + w * 8 + q;
        *(float4*)(attn + (size_t)qg * HID + h * HD + lane * 4) =
            make_float4(O[q][0] * inv, O[q][1] * inv, O[q][2] * inv, O[q][3] * inv);
    }
}

// ---------------------------------------------------------------------------
extern "C" void kernel_launch(void* const* d_in, const int* in_sizes, int n_in,
                              void* d_out, int out_size)
{
    const float* X   = (const float*)d_in[0];   // hidden_states [1,2048,2048]
    // d_in[1] = attention_mask (pure causal additive; applied analytically)
    const int*   pos = (const int*)d_in[2];     // position_ids int32
    const float* Wa  = (const float*)d_in[3];   // W_attn [2048,3072]
    const float* Wp  = (const float*)d_in[4];   // W_proj [2048,2048]
    float* out = (float*)d_out;

    float *qkv, *attn;
    __nv_bfloat16 *Xhi, *Xlo, *WaThi, *WaTlo, *WpThi, *WpTlo, *Ahi, *Alo;
    cudaGetSymbolAddress((void**)&qkv,   g_qkv);
    cudaGetSymbolAddress((void**)&attn,  g_attn);
    cudaGetSymbolAddress((void**)&Xhi,   g_Xhi);
    cudaGetSymbolAddress((void**)&Xlo,   g_Xlo);
    cudaGetSymbolAddress((void**)&WaThi, g_WaThi);
    cudaGetSymbolAddress((void**)&WaTlo, g_WaTlo);
    cudaGetSymbolAddress((void**)&WpThi, g_WpThi);
    cudaGetSymbolAddress((void**)&WpTlo, g_WpTlo);
    cudaGetSymbolAddress((void**)&Ahi,   g_Ahi);
    cudaGetSymbolAddress((void**)&Alo,   g_Alo);

    cudaFuncSetAttribute(gemm_bf16x3_kernel, cudaFuncAttributeMaxDynamicSharedMemorySize, GSMEM);
    cudaFuncSetAttribute(flash_kernel, cudaFuncAttributeMaxDynamicSharedMemorySize, SMEM_FLASH);

    // 1) split X; transpose+split Wa
    split_kernel<<<(S_LEN * HID + 255) / 256, 256>>>(X, Xhi, Xlo, S_LEN * HID);
    transpose_split_kernel<<<dim3(HID / 32, QKV_N / 32), dim3(32, 8)>>>(Wa, WaThi, WaTlo, HID, QKV_N);

    // 2) QKV = X @ Wa  (HMMA bf16 x3 split)
    gemm_bf16x3_kernel<<<dim3(QKV_N / 128, S_LEN / 128), 256, GSMEM>>>(
        Xhi, Xlo, WaThi, WaTlo, qkv, S_LEN, QKV_N, HID);

    // 3) RoPE in place on q + k heads
    rope_kernel<<<dim3(S_LEN, NH + NKV), HD>>>(pos, qkv);

    // 4) causal flash attention -> attn
    flash_kernel<<<dim3(S_LEN / BQ, NH), 256, SMEM_FLASH>>>(qkv, attn);

    // 5) split attn; transpose+split Wp; out = attn @ Wp
    split_kernel<<<(S_LEN * HID + 255) / 256, 256>>>(attn, Ahi, Alo, S_LEN * HID);
    transpose_split_kernel<<<dim3(HID / 32, HID / 32), dim3(32, 8)>>>(Wp, WpThi, WpTlo, HID, HID);
    gemm_bf16x3_kernel<<<dim3(HID / 128, S_LEN / 128), 256, GSMEM>>>(
        Ahi, Alo, WpThi, WpTlo, out, S_LEN, HID, HID);
}

// round 12
// speedup vs baseline: 1.7240x; 1.3506x over previous
#include <cuda_runtime.h>
#include <cuda_bf16.h>
#include <cstdint>
#include <math.h>

#define S_LEN 2048
#define HID   2048
#define NH    16
#define NKV   4
#define HD    128
#define QKV_N 3072
#define SCALE 0.08838834764831845f   // 128^-0.5

// ---------------------------------------------------------------------------
// Scratch (device globals — no allocation allowed)
// ---------------------------------------------------------------------------
__device__ float g_qkv[S_LEN * QKV_N];          // [S, 3072] fp32 = [q | k | v]
__device__ float g_attn[S_LEN * HID];

__device__ __nv_bfloat16 g_Xhi[S_LEN * HID];
__device__ __nv_bfloat16 g_Xlo[S_LEN * HID];
__device__ __nv_bfloat16 g_WaThi[QKV_N * HID];
__device__ __nv_bfloat16 g_WaTlo[QKV_N * HID];
__device__ __nv_bfloat16 g_WpThi[HID * HID];
__device__ __nv_bfloat16 g_WpTlo[HID * HID];
__device__ __nv_bfloat16 g_Ahi[S_LEN * HID];
__device__ __nv_bfloat16 g_Alo[S_LEN * HID];

// post-RoPE split Q/K and split V for HMMA flash
__device__ __nv_bfloat16 g_Qhi[S_LEN * HID];    // [S, 16*128]
__device__ __nv_bfloat16 g_Qlo[S_LEN * HID];
__device__ __nv_bfloat16 g_Khi[S_LEN * 512];    // [S, 4*128]
__device__ __nv_bfloat16 g_Klo[S_LEN * 512];
__device__ __nv_bfloat16 g_Vhi[S_LEN * 512];
__device__ __nv_bfloat16 g_Vlo[S_LEN * 512];

// ---------------------------------------------------------------------------
// Helpers (baseline ISA only)
// ---------------------------------------------------------------------------
__device__ __forceinline__ uint32_t smem_u32(const void* p) {
    uint32_t a;
    asm("{ .reg .u64 t; cvta.to.shared.u64 t, %1; cvt.u32.u64 %0, t; }" : "=r"(a) : "l"(p));
    return a;
}
__device__ __forceinline__ uint32_t swz128(uint32_t b) { return b ^ ((b >> 3) & 0x70); }
__device__ __forceinline__ uint32_t swz256(uint32_t b) { return b ^ ((b >> 4) & 0x70); }

#define LDSM_X4(r, a) \
    asm volatile("ldmatrix.sync.aligned.m8n8.x4.shared.b16 {%0,%1,%2,%3}, [%4];" \
        : "=r"((r)[0]), "=r"((r)[1]), "=r"((r)[2]), "=r"((r)[3]) : "r"(a))

#define LDSM_X4_T(r, a) \
    asm volatile("ldmatrix.sync.aligned.m8n8.x4.trans.shared.b16 {%0,%1,%2,%3}, [%4];" \
        : "=r"((r)[0]), "=r"((r)[1]), "=r"((r)[2]), "=r"((r)[3]) : "r"(a))

#define MMA_BF16(d, a, b0, b1) \
    asm volatile("mma.sync.aligned.m16n8k16.row.col.f32.bf16.bf16.f32 " \
        "{%0,%1,%2,%3}, {%4,%5,%6,%7}, {%8,%9}, {%0,%1,%2,%3};" \
        : "+f"((d)[0]), "+f"((d)[1]), "+f"((d)[2]), "+f"((d)[3]) \
        : "r"((a)[0]), "r"((a)[1]), "r"((a)[2]), "r"((a)[3]), "r"(b0), "r"(b1))

// A-operand variant with explicit 4 regs (for in-register P fragments)
#define MMA_BF16R(d, a0, a1, a2, a3, b0, b1) \
    asm volatile("mma.sync.aligned.m16n8k16.row.col.f32.bf16.bf16.f32 " \
        "{%0,%1,%2,%3}, {%4,%5,%6,%7}, {%8,%9}, {%0,%1,%2,%3};" \
        : "+f"((d)[0]), "+f"((d)[1]), "+f"((d)[2]), "+f"((d)[3]) \
        : "r"(a0), "r"(a1), "r"(a2), "r"(a3), "r"(b0), "r"(b1))

#define CP16(dst, src) \
    asm volatile("cp.async.cg.shared.global [%0], [%1], 16;" :: "r"(dst), "l"(src))
#define CP_COMMIT() asm volatile("cp.async.commit_group;" ::: "memory")
#define CP_WAIT1()  asm volatile("cp.async.wait_group 1;" ::: "memory")

__device__ __forceinline__ uint32_t packbf(float lo, float hi) {
    __nv_bfloat162 t = __floats2bfloat162_rn(lo, hi);
    return *(uint32_t*)&t;
}

// ---------------------------------------------------------------------------
// Prep: fp32 -> (hi, lo) bf16 split, elementwise
// ---------------------------------------------------------------------------
__global__ void split_kernel(const float* __restrict__ x,
                             __nv_bfloat16* __restrict__ hi,
                             __nv_bfloat16* __restrict__ lo, int n)
{
    int i = blockIdx.x * blockDim.x + threadIdx.x;
    if (i >= n) return;
    float v = x[i];
    __nv_bfloat16 h = __float2bfloat16_rn(v);
    hi[i] = h;
    lo[i] = __float2bfloat16_rn(v - __bfloat162float(h));
}

// Transpose + split: W[K,N] fp32 -> T{hi,lo}[N,K] bf16
__global__ void transpose_split_kernel(const float* __restrict__ W,
                                       __nv_bfloat16* __restrict__ Thi,
                                       __nv_bfloat16* __restrict__ Tlo, int K, int N)
{
    __shared__ float t[32][33];
    int k0 = blockIdx.x * 32, n0 = blockIdx.y * 32;
    int tx = threadIdx.x, ty = threadIdx.y;
    #pragma unroll
    for (int i = 0; i < 4; i++)
        t[ty + i * 8][tx] = W[(size_t)(k0 + ty + i * 8) * N + n0 + tx];
    __syncthreads();
    #pragma unroll
    for (int i = 0; i < 4; i++) {
        float v = t[tx][ty + i * 8];
        __nv_bfloat16 h = __float2bfloat16_rn(v);
        size_t o = (size_t)(n0 + ty + i * 8) * K + k0 + tx;
        Thi[o] = h;
        Tlo[o] = __float2bfloat16_rn(v - __bfloat162float(h));
    }
}

// ---------------------------------------------------------------------------
// GEMM via mma.sync bf16 x3 split (validated R11: rel_err 2.7e-5)
// ---------------------------------------------------------------------------
#define GT      16384
#define GSTAGE  65536
#define GSMEM   131072

__global__ __launch_bounds__(256) void gemm_bf16x3_kernel(
    const __nv_bfloat16* __restrict__ Ahi, const __nv_bfloat16* __restrict__ Alo,
    const __nv_bfloat16* __restrict__ Bhi, const __nv_bfloat16* __restrict__ Blo,
    float* __restrict__ C, int M, int N, int K)
{
    extern __shared__ char smc[];
    const uint32_t smem = smem_u32(smc);
    const int tid = threadIdx.x;
    const int wid = tid >> 5, lane = tid & 31;
    const int m0 = blockIdx.y * 128, n0 = blockIdx.x * 128;
    const int wm = wid & 1, wn = wid >> 1;

    float acc[4][4][4];
    #pragma unroll
    for (int a = 0; a < 4; a++)
        #pragma unroll
        for (int b = 0; b < 4; b++)
            #pragma unroll
            for (int c = 0; c < 4; c++) acc[a][b][c] = 0.0f;

    const int nkt = K >> 6;

    auto fill = [&](int s, int kt) {
        #pragma unroll
        for (int t = 0; t < 4; t++) {
            int idx = tid + t * 256;
            int row = idx >> 3, c16 = idx & 7;
            uint32_t dst = smem + s * GSTAGE + swz128(row * 128 + c16 * 16);
            size_t ka = (size_t)(m0 + row) * K + kt * 64 + c16 * 8;
            size_t kb = (size_t)(n0 + row) * K + kt * 64 + c16 * 8;
            CP16(dst,          Ahi + ka);
            CP16(dst + GT,     Alo + ka);
            CP16(dst + 2 * GT, Bhi + kb);
            CP16(dst + 3 * GT, Blo + kb);
        }
        CP_COMMIT();
    };

    fill(0, 0);

    const int r16 = lane & 15, chi = lane >> 4;

    for (int kt = 0; kt < nkt; kt++) {
        if (kt + 1 < nkt) fill((kt + 1) & 1, kt + 1);
        else CP_COMMIT();
        CP_WAIT1();
        __syncthreads();

        const uint32_t Ab = smem + (kt & 1) * GSTAGE;
        const uint32_t Bb = Ab + 2 * GT;

        #pragma unroll
        for (int ks = 0; ks < 4; ks++) {
            uint32_t a_hi[4][4], a_lo[4][4], b_hi[2][4], b_lo[2][4];
            #pragma unroll
            for (int mt = 0; mt < 4; mt++) {
                uint32_t off = swz128((wm * 64 + mt * 16 + r16) * 128 + (ks * 2 + chi) * 16);
                LDSM_X4(a_hi[mt], Ab + off);
                LDSM_X4(a_lo[mt], Ab + GT + off);
            }
            #pragma unroll
            for (int h = 0; h < 2; h++) {
                uint32_t off = swz128((wn * 32 + h * 16 + r16) * 128 + (ks * 2 + chi) * 16);
                LDSM_X4(b_hi[h], Bb + off);
                LDSM_X4(b_lo[h], Bb + GT + off);
            }
            #pragma unroll
            for (int mt = 0; mt < 4; mt++)
                #pragma unroll
                for (int nt = 0; nt < 4; nt++) {
                    int h = nt >> 1, o = nt & 1;
                    MMA_BF16(acc[mt][nt], a_hi[mt], b_hi[h][o], b_hi[h][o + 2]);
                    MMA_BF16(acc[mt][nt], a_hi[mt], b_lo[h][o], b_lo[h][o + 2]);
                    MMA_BF16(acc[mt][nt], a_lo[mt], b_hi[h][o], b_hi[h][o + 2]);
                }
        }
        __syncthreads();
    }

    #pragma unroll
    for (int mt = 0; mt < 4; mt++) {
        int row = m0 + wm * 64 + mt * 16 + (lane >> 2);
        #pragma unroll
        for (int nt = 0; nt < 4; nt++) {
            int col = n0 + wn * 32 + nt * 8 + (lane & 3) * 2;
            *(float2*)&C[(size_t)row * N + col] =
                make_float2(acc[mt][nt][0], acc[mt][nt][1]);
            *(float2*)&C[(size_t)(row + 8) * N + col] =
                make_float2(acc[mt][nt][2], acc[mt][nt][3]);
        }
    }
}

// ---------------------------------------------------------------------------
// RoPE + split: reads fp32 qkv, writes bf16 hi/lo Q (rope), K (rope), V (plain).
// grid (S, 24): heads 0-15 q, 16-19 k, 20-23 v. Double-trig faithful, fp64.
// ---------------------------------------------------------------------------
__global__ void rope_split_kernel(const int* __restrict__ pos,
                                  const float* __restrict__ qkv)
{
    const int s = blockIdx.x;
    const int head = blockIdx.y;
    const int d = threadIdx.x;             // 0..127

    if (head < NH + NKV) {                 // q or k: rope
        int base = (head < NH) ? head * HD : HID + (head - NH) * HD;
        const float* row = qkv + (size_t)s * QKV_N + base;
        float x  = row[d];
        float xp = row[d ^ 64];
        const int i = d & 63;
        double p   = (double)pos[s];
        double inv = exp(-((double)(2 * i) / 128.0) * log(10000.0));
        double f   = p * inv;
        double e   = (d < 64) ? sin(f) : cos(f);
        float  c   = (float)cos(e);
        float  sn  = (float)sin(e);
        float  partner = (d < 64) ? -xp : xp;
        float  v = x * c + partner * sn;
        __nv_bfloat16 h = __float2bfloat16_rn(v);
        __nv_bfloat16 l = __float2bfloat16_rn(v - __bfloat162float(h));
        if (head < NH) {
            size_t o = (size_t)s * HID + head * HD + d;
            g_Qhi[o] = h; g_Qlo[o] = l;
        } else {
            size_t o = (size_t)s * 512 + (head - NH) * HD + d;
            g_Khi[o] = h; g_Klo[o] = l;
        }
    } else {                               // v: plain split
        int hv = head - NH - NKV;
        float v = qkv[(size_t)s * QKV_N + HID + 512 + hv * HD + d];
        __nv_bfloat16 h = __float2bfloat16_rn(v);
        __nv_bfloat16 l = __float2bfloat16_rn(v - __bfloat162float(h));
        size_t o = (size_t)s * 512 + hv * HD + d;
        g_Vhi[o] = h; g_Vlo[o] = l;
    }
}

// ---------------------------------------------------------------------------
// HMMA flash attention (bf16x3 scores + bf16x3 P·V, fp32 softmax state).
// Block: 128 queries x 1 head, 8 warps; warp owns 16 full rows.
// KV tiles of 64 keys, cp.async double-buffered. 192KB smem, 1 CTA/SM.
// Smem tiles use 256B rows with swz256; P stays in registers (D-frag == A-frag).
// ---------------------------------------------------------------------------
#define FBQ 128
#define FBK 64
#define FQHI 0
#define FQLO 32768
#define FSTG(s) (65536 + (s) * 65536)
#define FKHI 0
#define FKLO 16384
#define FVHI 32768
#define FVLO 49152
#define FSMEM 196608

__global__ __launch_bounds__(256) void flash_hmma_kernel(float* __restrict__ attn)
{
    extern __shared__ char smf[];
    const uint32_t smem = smem_u32(smf);
    const int qt = blockIdx.x;             // 0..15
    const int h  = blockIdx.y;             // 0..15
    const int hk = h >> 2;
    const int tid = threadIdx.x;
    const int wid = tid >> 5, lane = tid & 31;
    const int r16 = lane & 15, chi = lane >> 4;

    // ---- stage Q (hi/lo), group 0 ----
    #pragma unroll
    for (int t = 0; t < 8; t++) {
        int idx = tid + t * 256;           // 0..2047
        int row = idx >> 4, c16 = idx & 15;
        uint32_t off = swz256(row * 256 + c16 * 16);
        size_t src = (size_t)(qt * FBQ + row) * HID + h * HD + c16 * 8;
        CP16(smem + FQHI + off, g_Qhi + src);
        CP16(smem + FQLO + off, g_Qlo + src);
    }
    CP_COMMIT();

    auto fill_kv = [&](int s, int kt) {
        #pragma unroll
        for (int t = 0; t < 4; t++) {
            int idx = tid + t * 256;       // 0..1023
            int row = idx >> 4, c16 = idx & 15;
            uint32_t off = swz256(row * 256 + c16 * 16);
            size_t src = (size_t)(kt * FBK + row) * 512 + hk * HD + c16 * 8;
            uint32_t base = smem + FSTG(s);
            CP16(base + FKHI + off, g_Khi + src);
            CP16(base + FKLO + off, g_Klo + src);
            CP16(base + FVHI + off, g_Vhi + src);
            CP16(base + FVLO + off, g_Vlo + src);
        }
        CP_COMMIT();
    };

    const int ktmax = 2 * qt + 1;
    fill_kv(0, 0);

    float O[16][4];
    #pragma unroll
    for (int nt = 0; nt < 16; nt++)
        O[nt][0] = O[nt][1] = O[nt][2] = O[nt][3] = 0.0f;
    float m0 = -1e30f, m1 = -1e30f, l0 = 0.0f, l1 = 0.0f;

    const int qg0 = qt * FBQ + wid * 16 + (lane >> 2);   // this lane's rows
    const int cql = (lane & 3) * 2;                      // col-pair base within n8

    for (int kt = 0; kt <= ktmax; kt++) {
        if (kt + 1 <= ktmax) fill_kv((kt + 1) & 1, kt + 1);
        else CP_COMMIT();
        CP_WAIT1();
        __syncthreads();

        const uint32_t Kb = smem + FSTG(kt & 1);

        // ---- phase 1: S[16 x 64] = Q . K^T (bf16 x3) ----
        float s[8][4];
        #pragma unroll
        for (int nt = 0; nt < 8; nt++)
            s[nt][0] = s[nt][1] = s[nt][2] = s[nt][3] = 0.0f;

        #pragma unroll
        for (int ks = 0; ks < 8; ks++) {
            uint32_t a_hi[4], a_lo[4], b_hi[4][4], b_lo[4][4];
            uint32_t qoff = swz256((wid * 16 + r16) * 256 + (ks * 2 + chi) * 16);
            LDSM_X4(a_hi, smem + FQHI + qoff);
            LDSM_X4(a_lo, smem + FQLO + qoff);
            #pragma unroll
            for (int g = 0; g < 4; g++) {
                uint32_t off = swz256((g * 16 + r16) * 256 + (ks * 2 + chi) * 16);
                LDSM_X4(b_hi[g], Kb + FKHI + off);
                LDSM_X4(b_lo[g], Kb + FKLO + off);
            }
            #pragma unroll
            for (int nt = 0; nt < 8; nt++) {
                int g = nt >> 1, o = nt & 1;
                MMA_BF16(s[nt], a_hi, b_hi[g][o], b_hi[g][o + 2]);
                MMA_BF16(s[nt], a_hi, b_lo[g][o], b_lo[g][o + 2]);
                MMA_BF16(s[nt], a_lo, b_hi[g][o], b_hi[g][o + 2]);
            }
        }

        // ---- scale + causal mask ----
        if (kt >= 2 * qt) {
            #pragma unroll
            for (int nt = 0; nt < 8; nt++) {
                int kg = kt * FBK + nt * 8 + cql;
                s[nt][0] = (kg     > qg0)     ? -1e30f : s[nt][0] * SCALE;
                s[nt][1] = (kg + 1 > qg0)     ? -1e30f : s[nt][1] * SCALE;
                s[nt][2] = (kg     > qg0 + 8) ? -1e30f : s[nt][2] * SCALE;
                s[nt][3] = (kg + 1 > qg0 + 8) ? -1e30f : s[nt][3] * SCALE;
            }
        } else {
            #pragma unroll
            for (int nt = 0; nt < 8; nt++) {
                s[nt][0] *= SCALE; s[nt][1] *= SCALE;
                s[nt][2] *= SCALE; s[nt][3] *= SCALE;
            }
        }

        // ---- online softmax (rows qg0 and qg0+8; quad-shuffle reductions) ----
        float t0 = -1e30f, t1 = -1e30f;
        #pragma unroll
        for (int nt = 0; nt < 8; nt++) {
            t0 = fmaxf(t0, fmaxf(s[nt][0], s[nt][1]));
            t1 = fmaxf(t1, fmaxf(s[nt][2], s[nt][3]));
        }
        t0 = fmaxf(t0, __shfl_xor_sync(0xffffffffu, t0, 1));
        t0 = fmaxf(t0, __shfl_xor_sync(0xffffffffu, t0, 2));
        t1 = fmaxf(t1, __shfl_xor_sync(0xffffffffu, t1, 1));
        t1 = fmaxf(t1, __shfl_xor_sync(0xffffffffu, t1, 2));
        float nm0 = fmaxf(m0, t0), nm1 = fmaxf(m1, t1);
        float corr0 = __expf(m0 - nm0), corr1 = __expf(m1 - nm1);
        float ps0 = 0.0f, ps1 = 0.0f;
        #pragma unroll
        for (int nt = 0; nt < 8; nt++) {
            s[nt][0] = __expf(s[nt][0] - nm0);
            s[nt][1] = __expf(s[nt][1] - nm0);
            s[nt][2] = __expf(s[nt][2] - nm1);
            s[nt][3] = __expf(s[nt][3] - nm1);
            ps0 += s[nt][0] + s[nt][1];
            ps1 += s[nt][2] + s[nt][3];
        }
        ps0 += __shfl_xor_sync(0xffffffffu, ps0, 1);
        ps0 += __shfl_xor_sync(0xffffffffu, ps0, 2);
        ps1 += __shfl_xor_sync(0xffffffffu, ps1, 1);
        ps1 += __shfl_xor_sync(0xffffffffu, ps1, 2);
        l0 = l0 * corr0 + ps0; m0 = nm0;
        l1 = l1 * corr1 + ps1; m1 = nm1;
        #pragma unroll
        for (int nt = 0; nt < 16; nt++) {
            O[nt][0] *= corr0; O[nt][1] *= corr0;
            O[nt][2] *= corr1; O[nt][3] *= corr1;
        }

        // ---- phase 2: O[16 x 128] += P . V (bf16 x3, P in registers) ----
        #pragma unroll
        for (int ks2 = 0; ks2 < 4; ks2++) {
            int b0 = 2 * ks2, b1 = b0 + 1;
            // hi fragments + reconstruct hi as fp32 via bit-shift for lo split
            uint32_t ph0 = packbf(s[b0][0], s[b0][1]);
            uint32_t ph1 = packbf(s[b0][2], s[b0][3]);
            uint32_t ph2 = packbf(s[b1][0], s[b1][1]);
            uint32_t ph3 = packbf(s[b1][2], s[b1][3]);
            float h00 = __uint_as_float(ph0 << 16), h01 = __uint_as_float(ph0 & 0xffff0000u);
            float h10 = __uint_as_float(ph1 << 16), h11 = __uint_as_float(ph1 & 0xffff0000u);
            float h20 = __uint_as_float(ph2 << 16), h21 = __uint_as_float(ph2 & 0xffff0000u);
            float h30 = __uint_as_float(ph3 << 16), h31 = __uint_as_float(ph3 & 0xffff0000u);
            uint32_t pl0 = packbf(s[b0][0] - h00, s[b0][1] - h01);
            uint32_t pl1 = packbf(s[b0][2] - h10, s[b0][3] - h11);
            uint32_t pl2 = packbf(s[b1][0] - h20, s[b1][1] - h21);
            uint32_t pl3 = packbf(s[b1][2] - h30, s[b1][3] - h31);

            #pragma unroll
            for (int d16 = 0; d16 < 8; d16++) {
                uint32_t vb_hi[4], vb_lo[4];
                uint32_t off = swz256((ks2 * 16 + r16) * 256 + (d16 * 2 + chi) * 16);
                LDSM_X4_T(vb_hi, Kb + FVHI + off);
                LDSM_X4_T(vb_lo, Kb + FVLO + off);
                int nt = d16 * 2;
                MMA_BF16R(O[nt],     ph0, ph1, ph2, ph3, vb_hi[0], vb_hi[1]);
                MMA_BF16R(O[nt],     ph0, ph1, ph2, ph3, vb_lo[0], vb_lo[1]);
                MMA_BF16R(O[nt],     pl0, pl1, pl2, pl3, vb_hi[0], vb_hi[1]);
                MMA_BF16R(O[nt + 1], ph0, ph1, ph2, ph3, vb_hi[2], vb_hi[3]);
                MMA_BF16R(O[nt + 1], ph0, ph1, ph2, ph3, vb_lo[2], vb_lo[3]);
                MMA_BF16R(O[nt + 1], pl0, pl1, pl2, pl3, vb_hi[2], vb_hi[3]);
            }
        }
        __syncthreads();   // stage consumed before next fill overwrites
    }

    // ---- epilogue ----
    float inv0 = 1.0f / l0, inv1 = 1.0f / l1;
    #pragma unroll
    for (int nt = 0; nt < 16; nt++) {
        int col = h * HD + nt * 8 + cql;
        *(float2*)&attn[(size_t)qg0 * HID + col] =
            make_float2(O[nt][0] * inv0, O[nt][1] * inv0);
        *(float2*)&attn[(size_t)(qg0 + 8) * HID + col] =
            make_float2(O[nt][2] * inv1, O[nt][3] * inv1);
    }
}

// ---------------------------------------------------------------------------
extern "C" void kernel_launch(void* const* d_in, const int* in_sizes, int n_in,
                              void* d_out, int out_size)
{
    const float* X   = (const float*)d_in[0];
    const int*   pos = (const int*)d_in[2];
    const float* Wa  = (const float*)d_in[3];
    const float* Wp  = (const float*)d_in[4];
    float* out = (float*)d_out;

    float *qkv, *attn;
    __nv_bfloat16 *Xhi, *Xlo, *WaThi, *WaTlo, *WpThi, *WpTlo, *Ahi, *Alo;
    cudaGetSymbolAddress((void**)&qkv,   g_qkv);
    cudaGetSymbolAddress((void**)&attn,  g_attn);
    cudaGetSymbolAddress((void**)&Xhi,   g_Xhi);
    cudaGetSymbolAddress((void**)&Xlo,   g_Xlo);
    cudaGetSymbolAddress((void**)&WaThi, g_WaThi);
    cudaGetSymbolAddress((void**)&WaTlo, g_WaTlo);
    cudaGetSymbolAddress((void**)&WpThi, g_WpThi);
    cudaGetSymbolAddress((void**)&WpTlo, g_WpTlo);
    cudaGetSymbolAddress((void**)&Ahi,   g_Ahi);
    cudaGetSymbolAddress((void**)&Alo,   g_Alo);

    cudaFuncSetAttribute(gemm_bf16x3_kernel, cudaFuncAttributeMaxDynamicSharedMemorySize, GSMEM);
    cudaFuncSetAttribute(flash_hmma_kernel, cudaFuncAttributeMaxDynamicSharedMemorySize, FSMEM);

    // 1) split X; transpose+split Wa
    split_kernel<<<(S_LEN * HID + 255) / 256, 256>>>(X, Xhi, Xlo, S_LEN * HID);
    transpose_split_kernel<<<dim3(HID / 32, QKV_N / 32), dim3(32, 8)>>>(Wa, WaThi, WaTlo, HID, QKV_N);

    // 2) QKV = X @ Wa
    gemm_bf16x3_kernel<<<dim3(QKV_N / 128, S_LEN / 128), 256, GSMEM>>>(
        Xhi, Xlo, WaThi, WaTlo, qkv, S_LEN, QKV_N, HID);

    // 3) RoPE + hi/lo split of Q, K, V
    rope_split_kernel<<<dim3(S_LEN, NH + 2 * NKV), HD>>>(pos, qkv);

    // 4) HMMA causal flash attention -> attn
    flash_hmma_kernel<<<dim3(S_LEN / FBQ, NH), 256, FSMEM>>>(attn);

    // 5) split attn; transpose+split Wp; out = attn @ Wp
    split_kernel<<<(S_LEN * HID + 255) / 256, 256>>>(attn, Ahi, Alo, S_LEN * HID);
    transpose_split_kernel<<<dim3(HID / 32, HID / 32), dim3(32, 8)>>>(Wp, WpThi, WpTlo, HID, HID);
    gemm_bf16x3_kernel<<<dim3(HID / 128, S_LEN / 128), 256, GSMEM>>>(
        Ahi, Alo, WpThi, WpTlo, out, S_LEN, HID, HID);
}